// round 8
// baseline (speedup 1.0000x reference)
#include <cuda_runtime.h>
#include <math_constants.h>

// SoftMinLayer: W = 79998 windows (len 500, step 250); 5 segments of 100;
// banded DTW (|i-j|<=1) over squared-L2 costs; out = mean(exp(-0.01*sqrt(d))).
//
// ONE WINDOW PER THREAD. Block = 128 threads = 128 windows. Per segment-stage:
// coalesced copy of each window's 100-float segment into a smem tile
// (rows 400B -> LDS.128 conflict-free), then each thread accumulates the <=3
// band cells of that stage from its own row (S via uniform broadcast LDS from
// a zero-padded -S table) and advances a 3-value banded-DTW recurrence.
// No warp reductions, no redundant DTW, no INF bookkeeping.

#define TPB  128
#define WPB  128
#define SEGC 5

typedef unsigned long long u64;

__device__ __forceinline__ u64 f2_fma(u64 a, u64 b, u64 c) {
    u64 d; asm("fma.rn.f32x2 %0, %1, %2, %3;" : "=l"(d) : "l"(a), "l"(b), "l"(c)); return d;
}
__device__ __forceinline__ u64 f2_add(u64 a, u64 b) {
    u64 d; asm("add.rn.f32x2 %0, %1, %2;" : "=l"(d) : "l"(a), "l"(b)); return d;
}
__device__ __forceinline__ float f2_hadd(u64 v) {
    float lo, hi; asm("mov.b64 {%0, %1}, %2;" : "=f"(lo), "=f"(hi) : "l"(v));
    return lo + hi;
}

__global__ void zero_kernel(float* out) { out[0] = 0.0f; }

__global__ __launch_bounds__(TPB)
void softmin_kernel(const float* __restrict__ x, const float* __restrict__ S,
                    float* __restrict__ out, int W, float invW)
{
    extern __shared__ float sm[];
    float* xs   = sm;                 // WPB * 100 floats = 51200 B stage tile
    float* sneg = sm + WPB * 100;     // 600 floats: -S (5 rows of 100) + zero row
    float* sred = sneg + 600;         // 4 floats

    const int t = threadIdx.x;
    for (int i = t; i < 600; i += TPB) sneg[i] = (i < 500) ? -S[i] : 0.0f;

    const int  wb    = blockIdx.x * WPB;
    const int  w     = wb + t;
    const bool valid = (w < W);
    const bool edge  = (wb + WPB > W);

    const u64* x2  = reinterpret_cast<const u64*>(x);
    u64*       xs2 = reinterpret_cast<u64*>(xs);
    u64*       dstp = xs2 + t;                     // dst f2 index n = t + 128r

    // copy-index state: n = t + 128r = win*50 + e2 (f2 units within stage)
    const int win0 = t / 50;
    const int e20  = t - win0 * 50;
    // fast-path src base (f2): (wb+win)*125 + e2  (+ m*50 per stage)
    const long base_fast = (long)(wb + win0) * 125 + e20;

    float pB = 0.0f, pC = 0.0f, pD = 0.0f;   // banded DTW carries
    const float INF = CUDART_INF_F;

    const ulonglong2* xrow = reinterpret_cast<const ulonglong2*>(xs + t * 100);

#pragma unroll
    for (int m = 0; m < SEGC; ++m) {
        __syncthreads();   // previous stage's readers are done

        // ---- stage copy: segment m of all WPB windows ----
        if (!edge) {
            long src = base_fast + m * 50;
            int  e2  = e20;
#pragma unroll 10
            for (int r = 0; r < 50; ++r) {
                dstp[128 * r] = x2[src];
                e2 += 28; src += 278;
                if (e2 >= 50) { e2 -= 50; src += 75; }
            }
        } else {
            int win = win0, e2 = e20;
#pragma unroll 10
            for (int r = 0; r < 50; ++r) {
                int wcv = wb + win; if (wcv > W - 1) wcv = W - 1;
                dstp[128 * r] = x2[(long)wcv * 125 + m * 50 + e2];
                e2 += 28; win += 2;
                if (e2 >= 50) { e2 -= 50; win += 1; }
            }
        }
        __syncthreads();

        // ---- compute stage m: cells (m, m-1), (m, m), (m, m+1) ----
        const int jA = (m == 0) ? 5 : m - 1;     // row 5 = zero pad
        const int jB = m;
        const int jC = (m == SEGC - 1) ? 5 : m + 1;
        const ulonglong2* sA = reinterpret_cast<const ulonglong2*>(sneg + jA * 100);
        const ulonglong2* sB = reinterpret_cast<const ulonglong2*>(sneg + jB * 100);
        const ulonglong2* sC = reinterpret_cast<const ulonglong2*>(sneg + jC * 100);

        u64 aAl = 0, aAh = 0, aBl = 0, aBh = 0, aCl = 0, aCh = 0;
#pragma unroll 5
        for (int k = 0; k < 25; ++k) {
            ulonglong2 xv = xrow[k];
            ulonglong2 va = sA[k];
            ulonglong2 vb = sB[k];
            ulonglong2 vc = sC[k];
            u64 d;
            d = f2_add(xv.x, va.x); aAl = f2_fma(d, d, aAl);
            d = f2_add(xv.y, va.y); aAh = f2_fma(d, d, aAh);
            d = f2_add(xv.x, vb.x); aBl = f2_fma(d, d, aBl);
            d = f2_add(xv.y, vb.y); aBh = f2_fma(d, d, aBh);
            d = f2_add(xv.x, vc.x); aCl = f2_fma(d, d, aCl);
            d = f2_add(xv.y, vc.y); aCh = f2_fma(d, d, aCh);
        }
        float CA = f2_hadd(f2_add(aAl, aAh));
        float CB = f2_hadd(f2_add(aBl, aBh));
        float CC = f2_hadd(f2_add(aCl, aCh));

        // ---- banded DTW incremental update ----
        if (m == 0) {
            pC = CB;            // D[0][0] = C(0,0) + 0
            pD = CC + pC;       // D[0][1] = C(0,1) + D[0][0]
            pB = INF;
        } else {
            float j0 = CA + fminf(pB, pC);                  // D[m][m-1]
            float j1 = CB + fminf(fminf(pD, j0), pC);       // D[m][m]
            float j2 = CC + fminf(j1, pD);                  // D[m][m+1]
            pB = j0; pC = j1; pD = j2;
        }
    }

    // result = sqrt(D[4][4]) = sqrt(pC)
    float xi = valid ? __expf(-0.01f * sqrtf(pC)) : 0.0f;

    // block reduce -> one atomicAdd
    float v = xi;
    v += __shfl_xor_sync(0xffffffffu, v, 16);
    v += __shfl_xor_sync(0xffffffffu, v, 8);
    v += __shfl_xor_sync(0xffffffffu, v, 4);
    v += __shfl_xor_sync(0xffffffffu, v, 2);
    v += __shfl_xor_sync(0xffffffffu, v, 1);
    const int lane = t & 31, warp = t >> 5;
    if (lane == 0) sred[warp] = v;
    __syncthreads();
    if (t == 0)
        atomicAdd(out, (sred[0] + sred[1] + sred[2] + sred[3]) * invW);
}

extern "C" void kernel_launch(void* const* d_in, const int* in_sizes, int n_in,
                              void* d_out, int out_size)
{
    const float* x = (const float*)d_in[0];
    const float* S = (const float*)d_in[1];
    float* out = (float*)d_out;

    const int Q    = in_sizes[0];
    const int L    = in_sizes[1];       // 500
    const int step = L / 2;             // 250
    const int W    = (Q - L + step - 1) / step;   // 79998
    const float invW = 1.0f / (float)W;

    const int smem_bytes = (WPB * 100 + 600 + 8) * sizeof(float);   // ~53.7 KB
    cudaFuncSetAttribute(softmin_kernel,
                         cudaFuncAttributeMaxDynamicSharedMemorySize, smem_bytes);

    zero_kernel<<<1, 1>>>(out);
    const int blocks = (W + WPB - 1) / WPB;   // 625
    softmin_kernel<<<blocks, TPB, smem_bytes>>>(x, S, out, W, invW);
}

// round 9
// speedup vs baseline: 1.6049x; 1.6049x over previous
#include <cuda_runtime.h>
#include <math_constants.h>

// SoftMinLayer: W = 79998 windows (len 500, step 250); 5 segments of 100;
// banded DTW (|i-j|<=1) over squared-L2 costs; out = mean(exp(-0.01*sqrt(d))).
//
// TWO windows per warp (16-lane halves), persistent. Segment-major loop with
// xp carry only: cell (m-1,m) reuses carried x registers; S slices are read
// from smem per use (s[m] once, s[m-1] re-read) so the sp carry registers are
// freed -> fits 64 regs -> 4 CTAs/SM. Width-16 fold tree (14 shfl) reduces
// all 13 band cells at once; width-16 broadcasts feed a register DTW.

#define SEGC   5
#define TPB    256
#define NW     8          // warps per block
#define BLOCKS 592        // 4 * 148, persistent

typedef unsigned long long u64;

__device__ __forceinline__ u64 f2_fma(u64 a, u64 b, u64 c) {
    u64 d; asm("fma.rn.f32x2 %0, %1, %2, %3;" : "=l"(d) : "l"(a), "l"(b), "l"(c)); return d;
}
__device__ __forceinline__ u64 f2_add(u64 a, u64 b) {
    u64 d; asm("add.rn.f32x2 %0, %1, %2;" : "=l"(d) : "l"(a), "l"(b)); return d;
}
__device__ __forceinline__ float f2_hadd(u64 v) {
    float lo, hi; asm("mov.b64 {%0, %1}, %2;" : "=f"(lo), "=f"(hi) : "l"(v));
    return lo + hi;
}

__device__ __forceinline__ float foldstep(float A, float B, bool p, int o) {
    float v = p ? B : A;
    float u = p ? A : B;
    return v + __shfl_xor_sync(0xffffffffu, u, o);
}
// After the 4-level width-16 fold, cell n sits at lane (within each half):
#define SRCLANE16(n) ((((n) & 1) << 3) | ((((n) >> 1) & 1) << 2) | \
                      ((((n) >> 2) & 1) << 1) | (((n) >> 3) & 1))

__global__ void zero_kernel(float* out) { out[0] = 0.0f; }

__global__ __launch_bounds__(TPB, 4)
void softmin_kernel(const float* __restrict__ x, const float* __restrict__ S,
                    float* __restrict__ out, int W, float invW)
{
    __shared__ float ssf[SEGC * 128];   // -S, segments padded 100 -> 128 (zeros)
    __shared__ float sred[NW];

    const int t = threadIdx.x;
    for (int i = t; i < SEGC * 128; i += TPB) {
        int seg = i >> 7, off = i & 127;
        ssf[i] = (off < 100) ? -S[seg * 100 + off] : 0.0f;
    }
    __syncthreads();
    const u64* ss2 = reinterpret_cast<const u64*>(ssf);   // [seg*64 + idx]

    const int lane = t & 31, warp = t >> 5;
    const int h    = lane >> 4;        // which window of the pair
    const int sub  = lane & 15;        // lane within half
    const int gw   = blockIdx.x * NW + warp;
    const int TW   = gridDim.x * NW;
    const int NP   = (W + 1) >> 1;

    const bool p8 = (lane & 8) != 0;
    const bool p4 = (lane & 4) != 0;
    const bool p2 = (lane & 2) != 0;
    const bool p1 = (lane & 1) != 0;

    float xsum = 0.0f;

    for (int p = gw; p < NP; p += TW) {
        const int w  = 2 * p + h;
        const int wc = (w < W) ? w : (W - 1);
        const u64* xw = reinterpret_cast<const u64*>(x) + (size_t)wc * 125u;

        u64 acc[13];
#pragma unroll
        for (int c = 0; c < 13; ++c) acc[c] = 0ull;

        // cell ids: (m,m)=3m ; (m,m-1)=3m-1 ; (m-1,m)=3m-2
        u64 xp[4];
#pragma unroll
        for (int m = 0; m < SEGC; ++m) {
            u64 xv[4];
#pragma unroll
            for (int k = 0; k < 4; ++k) {
                const int idx = sub + 16 * k;
                xv[k] = (idx < 50) ? xw[m * 50 + idx] : 0ull;   // 50 f2/segment
            }
            // (m,m) and (m-1,m) share the freshly loaded sv = -s[m]
#pragma unroll
            for (int k = 0; k < 4; ++k) {
                const int idx = sub + 16 * k;
                u64 sv = ss2[m * 64 + idx];                     // zero-padded
                { u64 d = f2_add(xv[k], sv); acc[3 * m] = f2_fma(d, d, acc[3 * m]); }
                if (m > 0) {
                    u64 d = f2_add(xp[k], sv);
                    acc[3 * m - 2] = f2_fma(d, d, acc[3 * m - 2]);
                }
            }
            // (m,m-1): re-read -s[m-1] (transient, per-k)
            if (m > 0) {
#pragma unroll
                for (int k = 0; k < 4; ++k) {
                    const int idx = sub + 16 * k;
                    u64 svp = ss2[(m - 1) * 64 + idx];
                    u64 d = f2_add(xv[k], svp);
                    acc[3 * m - 1] = f2_fma(d, d, acc[3 * m - 1]);
                }
            }
#pragma unroll
            for (int k = 0; k < 4; ++k) xp[k] = xv[k];
        }

        // horizontal f32x2 add -> 13 per-lane partials
        float a0  = f2_hadd(acc[0]),  a1  = f2_hadd(acc[1]),  a2  = f2_hadd(acc[2]);
        float a3  = f2_hadd(acc[3]),  a4  = f2_hadd(acc[4]),  a5  = f2_hadd(acc[5]);
        float a6  = f2_hadd(acc[6]),  a7  = f2_hadd(acc[7]),  a8  = f2_hadd(acc[8]);
        float a9  = f2_hadd(acc[9]),  a10 = f2_hadd(acc[10]), a11 = f2_hadd(acc[11]);
        float a12 = f2_hadd(acc[12]);

        // width-16 fold tree: 14 shfl reduce all 13 cells (per half)
        float q0 = foldstep(a0,  a1,  p8, 8);
        float q1 = foldstep(a2,  a3,  p8, 8);
        float q2 = foldstep(a4,  a5,  p8, 8);
        float q3 = foldstep(a6,  a7,  p8, 8);
        float q4 = foldstep(a8,  a9,  p8, 8);
        float q5 = foldstep(a10, a11, p8, 8);
        float q6 = foldstep(a12, 0.0f, p8, 8);

        float r0 = foldstep(q0, q1, p4, 4);
        float r1 = foldstep(q2, q3, p4, 4);
        float r2 = foldstep(q4, q5, p4, 4);
        float r3 = foldstep(q6, 0.0f, p4, 4);

        float t0 = foldstep(r0, r1, p2, 2);
        float t1 = foldstep(r2, r3, p2, 2);

        float fin = foldstep(t0, t1, p1, 1);

        // broadcast within each 16-lane half
        float C13[13];
#pragma unroll
        for (int n = 0; n < 13; ++n)
            C13[n] = __shfl_sync(0xffffffffu, fin, SRCLANE16(n), 16);

        float C[SEGC][3];
#pragma unroll
        for (int i = 0; i < SEGC; ++i) {
#pragma unroll
            for (int jo = 0; jo < 3; ++jo) {
                const int j = i + jo - 1;
                if (j >= 0 && j < SEGC) {
                    const int c = (j == i) ? 3 * i : ((j < i) ? 3 * i - 1 : 3 * i + 1);
                    C[i][jo] = C13[c];
                } else {
                    C[i][jo] = 0.0f;
                }
            }
        }

        // banded DTW, fully unrolled in registers
        const float INF = CUDART_INF_F;
        float row[SEGC + 1];
        row[0] = 0.0f;
#pragma unroll
        for (int r = 1; r <= SEGC; ++r) row[r] = INF;
#pragma unroll
        for (int i = 0; i < SEGC; ++i) {
            float nrow[SEGC + 1];
#pragma unroll
            for (int r = 0; r <= SEGC; ++r) nrow[r] = INF;
            const int lo = (i > 0) ? (i - 1) : 0;
            const int hi = (i + 1 < SEGC) ? (i + 1) : (SEGC - 1);
#pragma unroll
            for (int j = 0; j < SEGC; ++j) {
                if (j >= lo && j <= hi) {
                    float prev = fminf(fminf(row[j + 1], nrow[j]), row[j]);
                    nrow[j + 1] = C[i][j - i + 1] + prev;
                }
            }
#pragma unroll
            for (int r = 0; r <= SEGC; ++r) row[r] = nrow[r];
        }

        float xi = __expf(-0.01f * sqrtf(row[SEGC]));
        if (w < W) xsum += xi;        // uniform within each half
    }

    // epilogue: lane 0 of each half carries its half's sum
    float v = (sub == 0) ? xsum : 0.0f;
    v += __shfl_xor_sync(0xffffffffu, v, 16);
    v += __shfl_xor_sync(0xffffffffu, v, 8);
    v += __shfl_xor_sync(0xffffffffu, v, 4);
    v += __shfl_xor_sync(0xffffffffu, v, 2);
    v += __shfl_xor_sync(0xffffffffu, v, 1);
    if ((t & 31) == 0) sred[warp] = v;
    __syncthreads();
    if (t == 0) {
        float s = 0.0f;
#pragma unroll
        for (int i = 0; i < NW; ++i) s += sred[i];
        atomicAdd(out, s * invW);
    }
}

extern "C" void kernel_launch(void* const* d_in, const int* in_sizes, int n_in,
                              void* d_out, int out_size)
{
    const float* x = (const float*)d_in[0];
    const float* S = (const float*)d_in[1];
    float* out = (float*)d_out;

    const int Q    = in_sizes[0];
    const int L    = in_sizes[1];       // 500
    const int step = L / 2;             // 250
    const int W    = (Q - L + step - 1) / step;   // 79998
    const float invW = 1.0f / (float)W;

    zero_kernel<<<1, 1>>>(out);
    softmin_kernel<<<BLOCKS, TPB>>>(x, S, out, W, invW);
}

// round 10
// speedup vs baseline: 1.7408x; 1.0847x over previous
#include <cuda_runtime.h>
#include <math_constants.h>

// SoftMinLayer: W = 79998 windows (len 500, step 250); 5 segments of 100;
// banded DTW (|i-j|<=1) over squared-L2 costs; out = mean(exp(-0.01*sqrt(d))).
//
// TWO windows per warp (16-lane halves), persistent. ALL 20 x loads of the
// window are front-batched (MLP=20, one latency exposure per window); S is
// read from smem per use. Width-16 fold tree (14 shfl) reduces all 13 band
// cells at once; width-16 broadcasts feed a register DTW shared by the half.

#define SEGC   5
#define TPB    256
#define NW     8          // warps per block
#define BLOCKS 444        // 3 * 148, persistent

typedef unsigned long long u64;

__device__ __forceinline__ u64 f2_fma(u64 a, u64 b, u64 c) {
    u64 d; asm("fma.rn.f32x2 %0, %1, %2, %3;" : "=l"(d) : "l"(a), "l"(b), "l"(c)); return d;
}
__device__ __forceinline__ u64 f2_add(u64 a, u64 b) {
    u64 d; asm("add.rn.f32x2 %0, %1, %2;" : "=l"(d) : "l"(a), "l"(b)); return d;
}
__device__ __forceinline__ float f2_hadd(u64 v) {
    float lo, hi; asm("mov.b64 {%0, %1}, %2;" : "=f"(lo), "=f"(hi) : "l"(v));
    return lo + hi;
}

__device__ __forceinline__ float foldstep(float A, float B, bool p, int o) {
    float v = p ? B : A;
    float u = p ? A : B;
    return v + __shfl_xor_sync(0xffffffffu, u, o);
}
// After the 4-level width-16 fold, cell n sits at lane (within each half):
#define SRCLANE16(n) ((((n) & 1) << 3) | ((((n) >> 1) & 1) << 2) | \
                      ((((n) >> 2) & 1) << 1) | (((n) >> 3) & 1))

__global__ void zero_kernel(float* out) { out[0] = 0.0f; }

__global__ __launch_bounds__(TPB, 3)
void softmin_kernel(const float* __restrict__ x, const float* __restrict__ S,
                    float* __restrict__ out, int W, float invW)
{
    __shared__ float ssf[SEGC * 128];   // -S, segments padded 100 -> 128 (zeros)
    __shared__ float sred[NW];

    const int t = threadIdx.x;
    for (int i = t; i < SEGC * 128; i += TPB) {
        int seg = i >> 7, off = i & 127;
        ssf[i] = (off < 100) ? -S[seg * 100 + off] : 0.0f;
    }
    __syncthreads();
    const u64* ss2 = reinterpret_cast<const u64*>(ssf);   // [seg*64 + idx]

    const int lane = t & 31, warp = t >> 5;
    const int h    = lane >> 4;        // which window of the pair
    const int sub  = lane & 15;        // lane within half
    const int gw   = blockIdx.x * NW + warp;
    const int TW   = gridDim.x * NW;
    const int NP   = (W + 1) >> 1;

    const bool p8 = (lane & 8) != 0;
    const bool p4 = (lane & 4) != 0;
    const bool p2 = (lane & 2) != 0;
    const bool p1 = (lane & 1) != 0;

    float xsum = 0.0f;

    for (int p = gw; p < NP; p += TW) {
        const int w  = 2 * p + h;
        const int wc = (w < W) ? w : (W - 1);
        const u64* xw = reinterpret_cast<const u64*>(x) + (size_t)wc * 125u;

        // ---- front-batched loads: all 20 LDG.64 issued together ----
        u64 xv[SEGC * 4];
#pragma unroll
        for (int m = 0; m < SEGC; ++m)
#pragma unroll
            for (int k = 0; k < 4; ++k) {
                const int idx = sub + 16 * k;
                xv[m * 4 + k] = (idx < 50) ? xw[m * 50 + idx] : 0ull;
            }

        u64 acc[13];
#pragma unroll
        for (int c = 0; c < 13; ++c) acc[c] = 0ull;

        // cell ids: (m,m)=3m ; (m,m-1)=3m-1 ; (m-1,m)=3m-2
#pragma unroll
        for (int m = 0; m < SEGC; ++m) {
            // (m,m) and (m-1,m) share sv = -s[m]
#pragma unroll
            for (int k = 0; k < 4; ++k) {
                const int idx = sub + 16 * k;
                u64 sv = ss2[m * 64 + idx];                 // zero-padded
                { u64 d = f2_add(xv[m * 4 + k], sv); acc[3 * m] = f2_fma(d, d, acc[3 * m]); }
                if (m > 0) {
                    u64 d = f2_add(xv[(m - 1) * 4 + k], sv);
                    acc[3 * m - 2] = f2_fma(d, d, acc[3 * m - 2]);
                }
            }
            // (m,m-1): re-read -s[m-1] (transient)
            if (m > 0) {
#pragma unroll
                for (int k = 0; k < 4; ++k) {
                    const int idx = sub + 16 * k;
                    u64 svp = ss2[(m - 1) * 64 + idx];
                    u64 d = f2_add(xv[m * 4 + k], svp);
                    acc[3 * m - 1] = f2_fma(d, d, acc[3 * m - 1]);
                }
            }
        }

        // horizontal f32x2 add -> 13 per-lane partials
        float a0  = f2_hadd(acc[0]),  a1  = f2_hadd(acc[1]),  a2  = f2_hadd(acc[2]);
        float a3  = f2_hadd(acc[3]),  a4  = f2_hadd(acc[4]),  a5  = f2_hadd(acc[5]);
        float a6  = f2_hadd(acc[6]),  a7  = f2_hadd(acc[7]),  a8  = f2_hadd(acc[8]);
        float a9  = f2_hadd(acc[9]),  a10 = f2_hadd(acc[10]), a11 = f2_hadd(acc[11]);
        float a12 = f2_hadd(acc[12]);

        // width-16 fold tree: 14 shfl reduce all 13 cells (per half)
        float q0 = foldstep(a0,  a1,  p8, 8);
        float q1 = foldstep(a2,  a3,  p8, 8);
        float q2 = foldstep(a4,  a5,  p8, 8);
        float q3 = foldstep(a6,  a7,  p8, 8);
        float q4 = foldstep(a8,  a9,  p8, 8);
        float q5 = foldstep(a10, a11, p8, 8);
        float q6 = foldstep(a12, 0.0f, p8, 8);

        float r0 = foldstep(q0, q1, p4, 4);
        float r1 = foldstep(q2, q3, p4, 4);
        float r2 = foldstep(q4, q5, p4, 4);
        float r3 = foldstep(q6, 0.0f, p4, 4);

        float t0 = foldstep(r0, r1, p2, 2);
        float t1 = foldstep(r2, r3, p2, 2);

        float fin = foldstep(t0, t1, p1, 1);

        // broadcast within each 16-lane half
        float C13[13];
#pragma unroll
        for (int n = 0; n < 13; ++n)
            C13[n] = __shfl_sync(0xffffffffu, fin, SRCLANE16(n), 16);

        float C[SEGC][3];
#pragma unroll
        for (int i = 0; i < SEGC; ++i) {
#pragma unroll
            for (int jo = 0; jo < 3; ++jo) {
                const int j = i + jo - 1;
                if (j >= 0 && j < SEGC) {
                    const int c = (j == i) ? 3 * i : ((j < i) ? 3 * i - 1 : 3 * i + 1);
                    C[i][jo] = C13[c];
                } else {
                    C[i][jo] = 0.0f;
                }
            }
        }

        // banded DTW, fully unrolled in registers
        const float INF = CUDART_INF_F;
        float row[SEGC + 1];
        row[0] = 0.0f;
#pragma unroll
        for (int r = 1; r <= SEGC; ++r) row[r] = INF;
#pragma unroll
        for (int i = 0; i < SEGC; ++i) {
            float nrow[SEGC + 1];
#pragma unroll
            for (int r = 0; r <= SEGC; ++r) nrow[r] = INF;
            const int lo = (i > 0) ? (i - 1) : 0;
            const int hi = (i + 1 < SEGC) ? (i + 1) : (SEGC - 1);
#pragma unroll
            for (int j = 0; j < SEGC; ++j) {
                if (j >= lo && j <= hi) {
                    float prev = fminf(fminf(row[j + 1], nrow[j]), row[j]);
                    nrow[j + 1] = C[i][j - i + 1] + prev;
                }
            }
#pragma unroll
            for (int r = 0; r <= SEGC; ++r) row[r] = nrow[r];
        }

        float xi = __expf(-0.01f * sqrtf(row[SEGC]));
        if (w < W) xsum += xi;        // uniform within each half
    }

    // epilogue: lane 0 of each half carries its half's sum
    float v = (sub == 0) ? xsum : 0.0f;
    v += __shfl_xor_sync(0xffffffffu, v, 16);
    v += __shfl_xor_sync(0xffffffffu, v, 8);
    v += __shfl_xor_sync(0xffffffffu, v, 4);
    v += __shfl_xor_sync(0xffffffffu, v, 2);
    v += __shfl_xor_sync(0xffffffffu, v, 1);
    if ((t & 31) == 0) sred[warp] = v;
    __syncthreads();
    if (t == 0) {
        float s = 0.0f;
#pragma unroll
        for (int i = 0; i < NW; ++i) s += sred[i];
        atomicAdd(out, s * invW);
    }
}

extern "C" void kernel_launch(void* const* d_in, const int* in_sizes, int n_in,
                              void* d_out, int out_size)
{
    const float* x = (const float*)d_in[0];
    const float* S = (const float*)d_in[1];
    float* out = (float*)d_out;

    const int Q    = in_sizes[0];
    const int L    = in_sizes[1];       // 500
    const int step = L / 2;             // 250
    const int W    = (Q - L + step - 1) / step;   // 79998
    const float invW = 1.0f / (float)W;

    zero_kernel<<<1, 1>>>(out);
    softmin_kernel<<<BLOCKS, TPB>>>(x, S, out, W, invW);
}